// round 16
// baseline (speedup 1.0000x reference)
#include <cuda_runtime.h>
#include <cuda_fp16.h>
#include <cstdint>

// GPTQ int4 dequant + GEMM, sm_103 HMMA path (tcgen05 rejected by non-'a' target).
//   out[M,N] = x[M,K] @ W[K,N],  W = s[g] * (unpack4(qweight) - (unpack4(qzeros)+1))
// M=4096, K=4096, N=11008, GROUPSIZE=128. fp16 tensors arrive upcast to fp32.
//
// Round 13: split into three kernels.
//   K0: x fp32->fp16 (xh_g, 32MB).
//   K1: W int4->fp16 [K,N] (wh_g, 90MB) via exact hsub2/hmul2 dequant.
//   K2: pure fp16 GEMM: BM=128 BN=128 BK=64, 256 thr (8 warps, 4Mx2N),
//       3-stage cp.async for A and B, 2 CTAs/SM. W+x ~fit L2 (122/126MB).

#define M_DIM 4096
#define K_DIM 4096
#define N_DIM 11008
#define BM 128
#define BN 128
#define BK 64
#define NKC (K_DIM / BK)    // 64 chunks
#define THREADS 256

#define AROW 72                              // 64 + 8 pad (halves)
#define BROW 136                             // 128 + 8 pad (halves)
#define A_STAGE (BM * AROW * 2)              // 18432 B
#define B_STAGE (BK * BROW * 2)              // 17408 B
#define SMEM_B_OFF (3 * A_STAGE)
#define SMEM_TOTAL (3 * (A_STAGE + B_STAGE)) // 107520 B -> 2 CTAs/SM

__device__ __half xh_g[(size_t)M_DIM * K_DIM];   // fp16 x
__device__ __half wh_g[(size_t)K_DIM * N_DIM];   // fp16 dequantized W [K,N]

// ---------------- K0: x fp32 -> fp16 ----------------
__global__ void convert_x_kernel(const float* __restrict__ x)
{
    size_t i = ((size_t)blockIdx.x * blockDim.x + threadIdx.x) * 8;
    float4 f0 = *reinterpret_cast<const float4*>(x + i);
    float4 f1 = *reinterpret_cast<const float4*>(x + i + 4);
    __half2 h0 = __floats2half2_rn(f0.x, f0.y);
    __half2 h1 = __floats2half2_rn(f0.z, f0.w);
    __half2 h2 = __floats2half2_rn(f1.x, f1.y);
    __half2 h3 = __floats2half2_rn(f1.z, f1.w);
    uint4 v;
    v.x = *reinterpret_cast<uint32_t*>(&h0);
    v.y = *reinterpret_cast<uint32_t*>(&h1);
    v.z = *reinterpret_cast<uint32_t*>(&h2);
    v.w = *reinterpret_cast<uint32_t*>(&h3);
    *reinterpret_cast<uint4*>(&xh_g[i]) = v;
}

// ---------------- K1: dequant W -> fp16 [K,N] ----------------
// grid (N/256, K/8); thread: one qweight word = 8 k-values for one n.
__global__ void dequant_w_kernel(const int*   __restrict__ qweight,
                                 const float* __restrict__ scales,
                                 const int*   __restrict__ qzeros)
{
    const int n  = blockIdx.x * 256 + threadIdx.x;
    const int kw = blockIdx.y;                 // 0..511
    const int g  = kw >> 4;                    // group = (kw*8)/128

    const uint32_t q = ((const uint32_t*)qweight)[(size_t)kw * N_DIM + n];
    int zw = qzeros[(size_t)g * (N_DIM / 8) + (n >> 3)];
    uint32_t zb = 0x6400u + (((uint32_t)(zw >> ((n & 7) * 4)) & 0xF) + 1u);
    uint32_t z2 = zb | (zb << 16);
    __half sh = __float2half_rn(scales[(size_t)g * N_DIM + n]);
    uint32_t sb = (uint32_t)*reinterpret_cast<uint16_t*>(&sh);
    uint32_t s2 = sb | (sb << 16);
    const __half2 zz = *reinterpret_cast<const __half2*>(&z2);
    const __half2 ss = *reinterpret_cast<const __half2*>(&s2);

    // pairs (v_i, v_{i+4}): t_i = ((q>>4i)&0x000f000f)|0x6400 -> fp16(v)+1024
    __half* wbase = &wh_g[(size_t)(kw * 8) * N_DIM + n];
#pragma unroll
    for (int i = 0; i < 4; i++) {
        uint32_t t = ((q >> (4 * i)) & 0x000f000fu) | 0x64006400u;
        __half2 p = __hmul2(__hsub2(*reinterpret_cast<__half2*>(&t), zz), ss);
        wbase[(size_t)i * N_DIM]       = __low2half(p);   // k = 8kw+i
        wbase[(size_t)(i + 4) * N_DIM] = __high2half(p);  // k = 8kw+i+4
    }
}

// ---------------- helpers ----------------
__device__ __forceinline__ void cp_async16(void* dst_smem, const void* src) {
    uint32_t d = (uint32_t)__cvta_generic_to_shared(dst_smem);
    asm volatile("cp.async.cg.shared.global [%0], [%1], 16;" :: "r"(d), "l"(src) : "memory");
}
__device__ __forceinline__ void cp_commit() {
    asm volatile("cp.async.commit_group;" ::: "memory");
}
template <int N>
__device__ __forceinline__ void cp_wait() {
    asm volatile("cp.async.wait_group %0;" :: "n"(N) : "memory");
}

// ---------------- K2: fp16 GEMM ----------------
__global__ __launch_bounds__(THREADS, 2)
void gemm_kernel(float* __restrict__ out)
{
    extern __shared__ char smem[];
    __half* As = reinterpret_cast<__half*>(smem);               // [3][128][72]
    __half* Bs = reinterpret_cast<__half*>(smem + SMEM_B_OFF);  // [3][64][136]

    const int tid  = threadIdx.x;
    const int lane = tid & 31;
    const int warp = tid >> 5;
    const int wm   = warp >> 1;   // 0..3 (32 rows)
    const int wn   = warp & 1;    // 0..1 (64 cols)
    const int bm   = blockIdx.y * BM;
    const int bn   = blockIdx.x * BN;

    float acc[2][8][4];
#pragma unroll
    for (int i = 0; i < 2; i++)
#pragma unroll
        for (int j = 0; j < 8; j++)
#pragma unroll
            for (int r = 0; r < 4; r++) acc[i][j][r] = 0.f;

    // A: 1024 16B-chunks/stage (128 rows x 8), 4/thread.
    // B: 1024 16B-chunks/stage (64 rows x 16), 4/thread.
    auto issue = [&](int c) {
        const int st = c % 3;
        __half* abase = As + (size_t)st * (A_STAGE / 2);
        __half* bbase = Bs + (size_t)st * (B_STAGE / 2);
#pragma unroll
        for (int it = 0; it < 4; it++) {
            int cc  = tid + it * THREADS;
            int row = cc >> 3;
            int col = (cc & 7) << 3;
            cp_async16(abase + row * AROW + col,
                       &xh_g[(size_t)(bm + row) * K_DIM + c * BK + col]);
        }
#pragma unroll
        for (int it = 0; it < 4; it++) {
            int cc  = tid + it * THREADS;
            int row = cc >> 4;
            int col = (cc & 15) << 3;
            cp_async16(bbase + row * BROW + col,
                       &wh_g[(size_t)(c * BK + row) * N_DIM + bn + col]);
        }
        cp_commit();
    };

    auto compute = [&](int c) {
        const int st = c % 3;
        const __half* abase = As + (size_t)st * (A_STAGE / 2);
        const __half* bbase = Bs + (size_t)st * (B_STAGE / 2);
#pragma unroll
        for (int ks = 0; ks < 4; ks++) {
            uint32_t a[2][4];
#pragma unroll
            for (int mt = 0; mt < 2; mt++) {
                const __half* p = abase +
                    (wm * 32 + mt * 16 + (lane & 15)) * AROW +
                    ks * 16 + (lane >> 4) * 8;
                uint32_t addr = (uint32_t)__cvta_generic_to_shared(p);
                asm volatile(
                    "ldmatrix.sync.aligned.m8n8.x4.shared.b16 {%0,%1,%2,%3}, [%4];"
                    : "=r"(a[mt][0]), "=r"(a[mt][1]), "=r"(a[mt][2]), "=r"(a[mt][3])
                    : "r"(addr));
            }
#pragma unroll
            for (int np = 0; np < 4; np++) {   // 16 n-cols per trans-ldmatrix
                const __half* p = bbase +
                    (ks * 16 + (lane & 15)) * BROW +
                    wn * 64 + np * 16 + (lane >> 4) * 8;
                uint32_t addr = (uint32_t)__cvta_generic_to_shared(p);
                uint32_t r0, r1, r2, r3;
                asm volatile(
                    "ldmatrix.sync.aligned.m8n8.x4.trans.shared.b16 {%0,%1,%2,%3}, [%4];"
                    : "=r"(r0), "=r"(r1), "=r"(r2), "=r"(r3)
                    : "r"(addr));
#pragma unroll
                for (int mt = 0; mt < 2; mt++) {
                    asm volatile(
                        "mma.sync.aligned.m16n8k16.row.col.f32.f16.f16.f32 "
                        "{%0,%1,%2,%3}, {%4,%5,%6,%7}, {%8,%9}, {%0,%1,%2,%3};"
                        : "+f"(acc[mt][np*2][0]), "+f"(acc[mt][np*2][1]),
                          "+f"(acc[mt][np*2][2]), "+f"(acc[mt][np*2][3])
                        : "r"(a[mt][0]), "r"(a[mt][1]), "r"(a[mt][2]), "r"(a[mt][3]),
                          "r"(r0), "r"(r1));
                    asm volatile(
                        "mma.sync.aligned.m16n8k16.row.col.f32.f16.f16.f32 "
                        "{%0,%1,%2,%3}, {%4,%5,%6,%7}, {%8,%9}, {%0,%1,%2,%3};"
                        : "+f"(acc[mt][np*2+1][0]), "+f"(acc[mt][np*2+1][1]),
                          "+f"(acc[mt][np*2+1][2]), "+f"(acc[mt][np*2+1][3])
                        : "r"(a[mt][0]), "r"(a[mt][1]), "r"(a[mt][2]), "r"(a[mt][3]),
                          "r"(r2), "r"(r3));
                }
            }
        }
    };

    // -------- prologue --------
    issue(0);
    issue(1);
    cp_wait<1>();
    __syncthreads();

    // -------- mainloop --------
    for (int c = 0; c < NKC; ++c) {
        compute(c);
        if (c + 2 < NKC) { issue(c + 2); cp_wait<1>(); }
        else             { cp_wait<0>(); }
        __syncthreads();
    }

    // -------- epilogue: round through fp16, store fp32 --------
#pragma unroll
    for (int mt = 0; mt < 2; mt++) {
        int row0 = bm + wm * 32 + mt * 16 + (lane >> 2);
#pragma unroll
        for (int nt = 0; nt < 8; nt++) {
            int col = bn + wn * 64 + nt * 8 + (lane & 3) * 2;
            float2 v0, v1;
            v0.x = __half2float(__float2half_rn(acc[mt][nt][0]));
            v0.y = __half2float(__float2half_rn(acc[mt][nt][1]));
            v1.x = __half2float(__float2half_rn(acc[mt][nt][2]));
            v1.y = __half2float(__float2half_rn(acc[mt][nt][3]));
            *reinterpret_cast<float2*>(&out[(size_t)row0 * N_DIM + col])       = v0;
            *reinterpret_cast<float2*>(&out[(size_t)(row0 + 8) * N_DIM + col]) = v1;
        }
    }
}

extern "C" void kernel_launch(void* const* d_in, const int* in_sizes, int n_in,
                              void* d_out, int out_size)
{
    // Identify inputs by element count (all distinct).
    const float* x       = nullptr;   // 16777216 (fp16 upcast to fp32)
    const int*   qweight = nullptr;   // 5636096
    const float* scales  = nullptr;   // 352256 (fp16 upcast to fp32)
    const int*   qzeros  = nullptr;   // 44032
    for (int i = 0; i < n_in; i++) {
        switch (in_sizes[i]) {
            case 16777216: x       = (const float*)d_in[i]; break;
            case 5636096:  qweight = (const int*)  d_in[i]; break;
            case 352256:   scales  = (const float*)d_in[i]; break;
            case 44032:    qzeros  = (const int*)  d_in[i]; break;
            default: break;
        }
    }
    float* out = (float*)d_out;

    convert_x_kernel<<<(size_t)M_DIM * K_DIM / (256 * 8), 256>>>(x);
    dequant_w_kernel<<<dim3(N_DIM / 256, K_DIM / 8), 256>>>(qweight, scales, qzeros);

    static bool attr_set = false;
    if (!attr_set) {
        cudaFuncSetAttribute(gemm_kernel,
                             cudaFuncAttributeMaxDynamicSharedMemorySize, SMEM_TOTAL);
        attr_set = true;
    }
    dim3 grid(N_DIM / BN, M_DIM / BM);   // (86, 32)
    gemm_kernel<<<grid, THREADS, SMEM_TOTAL>>>(out);
}

// round 17
// speedup vs baseline: 1.4310x; 1.4310x over previous
#include <cuda_runtime.h>
#include <cuda_fp16.h>
#include <cstdint>

// GPTQ int4 fused dequant + GEMM, sm_103 HMMA path.
//   out[M,N] = x[M,K] @ W[K,N],  W = s[g] * (unpack4(qweight) - (unpack4(qzeros)+1))
// M=4096, K=4096, N=11008, GROUPSIZE=128. fp16 tensors arrive upcast to fp32.
//
// Round 17: revert to fused round-12 structure (pre-dequant regressed: fp16 W
// traffic 4x int4). Reshape BM=128 BN=128 BK=64 @ 256 thr (8 warps, 4Mx2N,
// 32x64/warp) so SMEM=110.6KB and regs fit 2 CTAs/SM -> two independent
// barrier domains hide sync/cp_wait stalls. Marlin-style exact dequant with
// k-perm [0,4,1,5,2,6,3,7] baked into the A fp32->fp16 convert kernel.

#define M_DIM 4096
#define K_DIM 4096
#define N_DIM 11008
#define BM 128
#define BN 128
#define BK 64
#define NKC (K_DIM / BK)    // 64 chunks
#define THREADS 256

#define ROW_HALVES 72                       // 64 + 8 pad
#define A_STAGE (BM * ROW_HALVES * 2)       // 18432 B
#define B_STAGE (BN * ROW_HALVES * 2)       // 18432 B
#define SMEM_B_OFF (3 * A_STAGE)
#define SMEM_TOTAL (3 * (A_STAGE + B_STAGE))   // 110592 B -> 2 CTAs/SM

__device__ __half xh_g[(size_t)M_DIM * K_DIM];   // 32 MB fp16 x (k-permuted)

// ---------------- convert kernel: fp32->fp16, k-perm [0,4,1,5,2,6,3,7] ----
__global__ void convert_x_kernel(const float* __restrict__ x)
{
    size_t i = ((size_t)blockIdx.x * blockDim.x + threadIdx.x) * 8;
    float4 f0 = *reinterpret_cast<const float4*>(x + i);      // k 0..3
    float4 f1 = *reinterpret_cast<const float4*>(x + i + 4);  // k 4..7
    __half2 h0 = __floats2half2_rn(f0.x, f1.x);
    __half2 h1 = __floats2half2_rn(f0.y, f1.y);
    __half2 h2 = __floats2half2_rn(f0.z, f1.z);
    __half2 h3 = __floats2half2_rn(f0.w, f1.w);
    uint4 v;
    v.x = *reinterpret_cast<uint32_t*>(&h0);
    v.y = *reinterpret_cast<uint32_t*>(&h1);
    v.z = *reinterpret_cast<uint32_t*>(&h2);
    v.w = *reinterpret_cast<uint32_t*>(&h3);
    *reinterpret_cast<uint4*>(&xh_g[i]) = v;
}

// ---------------- helpers ----------------
__device__ __forceinline__ void cp_async16(void* dst_smem, const void* src) {
    uint32_t d = (uint32_t)__cvta_generic_to_shared(dst_smem);
    asm volatile("cp.async.cg.shared.global [%0], [%1], 16;" :: "r"(d), "l"(src) : "memory");
}
__device__ __forceinline__ void cp_commit() {
    asm volatile("cp.async.commit_group;" ::: "memory");
}
template <int N>
__device__ __forceinline__ void cp_wait() {
    asm volatile("cp.async.wait_group %0;" :: "n"(N) : "memory");
}

// ---------------- GEMM kernel ----------------
__global__ __launch_bounds__(THREADS, 2)
void gptq_gemm_kernel(const int*   __restrict__ qweight,
                      const float* __restrict__ scales,
                      const int*   __restrict__ qzeros,
                      float*       __restrict__ out)
{
    extern __shared__ char smem[];
    __half* As = reinterpret_cast<__half*>(smem);               // [3][128][72]
    __half* Bs = reinterpret_cast<__half*>(smem + SMEM_B_OFF);  // [3][128][72]

    const int tid  = threadIdx.x;
    const int lane = tid & 31;
    const int warp = tid >> 5;
    const int wm   = warp >> 1;   // 0..3 (32 rows)
    const int wn   = warp & 1;    // 0..1 (64 cols)
    const int bm   = blockIdx.y * BM;
    const int bn   = blockIdx.x * BN;

    float acc[2][8][4];
#pragma unroll
    for (int i = 0; i < 2; i++)
#pragma unroll
        for (int j = 0; j < 8; j++)
#pragma unroll
            for (int r = 0; r < 4; r++) acc[i][j][r] = 0.f;

    // ---- A cp.async: 1024 16B-chunks/stage, 4 per thread ----
    auto issueA = [&](int c) {
        const int st = c % 3;
        __half* abase = As + (size_t)st * (A_STAGE / 2);
#pragma unroll
        for (int it = 0; it < 4; it++) {
            int cc  = tid + it * THREADS;
            int row = cc >> 3;
            int col = (cc & 7) << 3;
            cp_async16(abase + row * ROW_HALVES + col,
                       &xh_g[(size_t)(bm + row) * K_DIM + c * BK + col]);
        }
        cp_commit();
    };

    // ---- B staging: thread owns n = tid&127, words kq = (tid>>7)*4 + 0..3 ----
    const int nloc = tid & 127;
    const int gn   = bn + nloc;
    const int kqh  = tid >> 7;        // 0..1
    uint32_t qv[4];
    uint32_t z2;                      // half2(1024+z, 1024+z) bits
    uint32_t s2;                      // half2(s, s) bits

    auto fetchB = [&](int c) {
        const int g = c >> 1;         // group = (c*64)/128
        int zw = qzeros[(size_t)g * (N_DIM / 8) + (gn >> 3)];
        uint32_t zb = 0x6400u + (((uint32_t)(zw >> ((gn & 7) * 4)) & 0xF) + 1u);
        z2 = zb | (zb << 16);
        __half sh = __float2half_rn(scales[(size_t)g * N_DIM + gn]);
        uint32_t sb = (uint32_t)*reinterpret_cast<uint16_t*>(&sh);
        s2 = sb | (sb << 16);
#pragma unroll
        for (int w = 0; w < 4; w++)
            qv[w] = ((const uint32_t*)qweight)[(size_t)(c * 8 + kqh * 4 + w) * N_DIM + gn];
    };

    auto storeB = [&](int c) {
        const int st = c % 3;
        __half* brow = Bs + (size_t)st * (B_STAGE / 2) + nloc * ROW_HALVES;
        const __half2 zz = *reinterpret_cast<const __half2*>(&z2);
        const __half2 ss = *reinterpret_cast<const __half2*>(&s2);
#pragma unroll
        for (int w = 0; w < 4; w++) {
            const uint32_t q = qv[w];
            uint32_t t0 = ( q        & 0x000f000fu) | 0x64006400u;  // (v0,v4)+1024
            uint32_t t1 = ((q >> 4)  & 0x000f000fu) | 0x64006400u;  // (v1,v5)+1024
            uint32_t t2 = ((q >> 8)  & 0x000f000fu) | 0x64006400u;  // (v2,v6)+1024
            uint32_t t3 = ((q >> 12) & 0x000f000fu) | 0x64006400u;  // (v3,v7)+1024
            __half2 p0 = __hmul2(__hsub2(*reinterpret_cast<__half2*>(&t0), zz), ss);
            __half2 p1 = __hmul2(__hsub2(*reinterpret_cast<__half2*>(&t1), zz), ss);
            __half2 p2 = __hmul2(__hsub2(*reinterpret_cast<__half2*>(&t2), zz), ss);
            __half2 p3 = __hmul2(__hsub2(*reinterpret_cast<__half2*>(&t3), zz), ss);
            uint4 v;
            v.x = *reinterpret_cast<uint32_t*>(&p0);
            v.y = *reinterpret_cast<uint32_t*>(&p1);
            v.z = *reinterpret_cast<uint32_t*>(&p2);
            v.w = *reinterpret_cast<uint32_t*>(&p3);
            *reinterpret_cast<uint4*>(brow + (kqh * 4 + w) * 8) = v;
        }
    };

    auto compute = [&](int c) {
        const int st = c % 3;
        const __half* abase = As + (size_t)st * (A_STAGE / 2);
        const __half* bbase = Bs + (size_t)st * (B_STAGE / 2);
#pragma unroll
        for (int ks = 0; ks < 4; ks++) {
            uint32_t a[2][4];
#pragma unroll
            for (int mt = 0; mt < 2; mt++) {
                const __half* p = abase +
                    (wm * 32 + mt * 16 + (lane & 15)) * ROW_HALVES +
                    ks * 16 + (lane >> 4) * 8;
                uint32_t addr = (uint32_t)__cvta_generic_to_shared(p);
                asm volatile(
                    "ldmatrix.sync.aligned.m8n8.x4.shared.b16 {%0,%1,%2,%3}, [%4];"
                    : "=r"(a[mt][0]), "=r"(a[mt][1]), "=r"(a[mt][2]), "=r"(a[mt][3])
                    : "r"(addr));
            }
#pragma unroll
            for (int np = 0; np < 4; np++) {   // 16 n-cols per ldmatrix (n-major)
                const __half* p = bbase +
                    (wn * 64 + np * 16 + ((lane >> 4) << 3) + (lane & 7)) * ROW_HALVES +
                    ks * 16 + (((lane >> 3) & 1) << 3);
                uint32_t addr = (uint32_t)__cvta_generic_to_shared(p);
                uint32_t r0, r1, r2, r3;
                asm volatile(
                    "ldmatrix.sync.aligned.m8n8.x4.shared.b16 {%0,%1,%2,%3}, [%4];"
                    : "=r"(r0), "=r"(r1), "=r"(r2), "=r"(r3)
                    : "r"(addr));
#pragma unroll
                for (int mt = 0; mt < 2; mt++) {
                    asm volatile(
                        "mma.sync.aligned.m16n8k16.row.col.f32.f16.f16.f32 "
                        "{%0,%1,%2,%3}, {%4,%5,%6,%7}, {%8,%9}, {%0,%1,%2,%3};"
                        : "+f"(acc[mt][np*2][0]), "+f"(acc[mt][np*2][1]),
                          "+f"(acc[mt][np*2][2]), "+f"(acc[mt][np*2][3])
                        : "r"(a[mt][0]), "r"(a[mt][1]), "r"(a[mt][2]), "r"(a[mt][3]),
                          "r"(r0), "r"(r1));
                    asm volatile(
                        "mma.sync.aligned.m16n8k16.row.col.f32.f16.f16.f32 "
                        "{%0,%1,%2,%3}, {%4,%5,%6,%7}, {%8,%9}, {%0,%1,%2,%3};"
                        : "+f"(acc[mt][np*2+1][0]), "+f"(acc[mt][np*2+1][1]),
                          "+f"(acc[mt][np*2+1][2]), "+f"(acc[mt][np*2+1][3])
                        : "r"(a[mt][0]), "r"(a[mt][1]), "r"(a[mt][2]), "r"(a[mt][3]),
                          "r"(r2), "r"(r3));
                }
            }
        }
    };

    // -------- prologue --------
    fetchB(0);
    issueA(0);
    issueA(1);
    storeB(0);
    fetchB(1);
    cp_wait<1>();
    __syncthreads();

    // -------- mainloop --------
    for (int c = 0; c < NKC; ++c) {
        if (c + 1 < NKC) storeB(c + 1);     // stage (c+1)%3 free (readers were c-2)
        if (c + 2 < NKC) fetchB(c + 2);     // LDGs hidden under compute
        compute(c);
        if (c + 2 < NKC) { issueA(c + 2); cp_wait<1>(); }
        else             { cp_wait<0>(); }
        __syncthreads();
    }

    // -------- epilogue: round through fp16, store fp32 --------
#pragma unroll
    for (int mt = 0; mt < 2; mt++) {
        int row0 = bm + wm * 32 + mt * 16 + (lane >> 2);
#pragma unroll
        for (int nt = 0; nt < 8; nt++) {
            int col = bn + wn * 64 + nt * 8 + (lane & 3) * 2;
            float2 v0, v1;
            v0.x = __half2float(__float2half_rn(acc[mt][nt][0]));
            v0.y = __half2float(__float2half_rn(acc[mt][nt][1]));
            v1.x = __half2float(__float2half_rn(acc[mt][nt][2]));
            v1.y = __half2float(__float2half_rn(acc[mt][nt][3]));
            *reinterpret_cast<float2*>(&out[(size_t)row0 * N_DIM + col])       = v0;
            *reinterpret_cast<float2*>(&out[(size_t)(row0 + 8) * N_DIM + col]) = v1;
        }
    }
}

extern "C" void kernel_launch(void* const* d_in, const int* in_sizes, int n_in,
                              void* d_out, int out_size)
{
    // Identify inputs by element count (all distinct).
    const float* x       = nullptr;   // 16777216 (fp16 upcast to fp32)
    const int*   qweight = nullptr;   // 5636096
    const float* scales  = nullptr;   // 352256 (fp16 upcast to fp32)
    const int*   qzeros  = nullptr;   // 44032
    for (int i = 0; i < n_in; i++) {
        switch (in_sizes[i]) {
            case 16777216: x       = (const float*)d_in[i]; break;
            case 5636096:  qweight = (const int*)  d_in[i]; break;
            case 352256:   scales  = (const float*)d_in[i]; break;
            case 44032:    qzeros  = (const int*)  d_in[i]; break;
            default: break;
        }
    }
    float* out = (float*)d_out;

    convert_x_kernel<<<(size_t)M_DIM * K_DIM / (256 * 8), 256>>>(x);

    static bool attr_set = false;
    if (!attr_set) {
        cudaFuncSetAttribute(gptq_gemm_kernel,
                             cudaFuncAttributeMaxDynamicSharedMemorySize, SMEM_TOTAL);
        attr_set = true;
    }
    dim3 grid(N_DIM / BN, M_DIM / BM);   // (86, 32)
    gptq_gemm_kernel<<<grid, THREADS, SMEM_TOTAL>>>(qweight, scales, qzeros, out);
}